// round 15
// baseline (speedup 1.0000x reference)
#include <cuda_runtime.h>

#define NB   32
#define DD   256
#define MMs  784
#define CINc 2048
#define MAT  (DD*DD)          // 65536
#define BMAT (NB*MAT)         // 2,097,152
#define STG  18432            // floats per mma stage (4 arrays of 4608)
#define MM_SMEM 147456        // 2 stages * 18432 floats * 4B
#define COV_SMEM 81920        // 2 stages * 10240 floats * 4B

// Scratch (device globals; no allocation anywhere)
__device__ float g_y[NB*DD*MMs];      // BN'd ReLU'd activations [b][d][m]
__device__ float g_mats[9u*BMAT];     // 9 batched 256x256 buffers
__device__ float g_small[16384];
// [0,256) bn_mean [256,512) bn_rstd [512,8704) rowmean
// [8704,8736) tr0 [8736,8768) tr_now [8768] jc [8772,8836) trp (NB*2)

// ---------------------------------------------------------------------------
__device__ __forceinline__ float warpReduce(float v) {
    #pragma unroll
    for (int o = 16; o; o >>= 1) v += __shfl_down_sync(0xffffffffu, v, o);
    return v;
}

__device__ __forceinline__ float sice_f(float L, float g12, float dec)
{
    float lp = fmaxf(L, 0.f);
    float lm = fmaxf(-L, 0.f);
    lp = fmaxf(lp - dec * (g12 + 0.07f), 0.f);
    lm = fmaxf(lm - dec * (-g12 + 0.07f), 0.f);
    return lp - lm;
}

__device__ __forceinline__ unsigned smem_u32(const void* p) {
    unsigned a;
    asm("{ .reg .u64 t; cvta.to.shared.u64 t, %1; cvt.u32.u64 %0, t; }"
        : "=r"(a) : "l"(p));
    return a;
}

// ---------------------------------------------------------------------------
// tf32 helpers
// ---------------------------------------------------------------------------
__device__ __forceinline__ float tf32r(float x) {
    unsigned u;
    asm("cvt.rna.tf32.f32 %0, %1;" : "=r"(u) : "f"(x));
    return __uint_as_float(u);
}
__device__ __forceinline__ void split4(float4 x, float4& hi, float4& lo) {
    hi.x = tf32r(x.x); lo.x = tf32r(x.x - hi.x);
    hi.y = tf32r(x.y); lo.y = tf32r(x.y - hi.y);
    hi.z = tf32r(x.z); lo.z = tf32r(x.z - hi.z);
    hi.w = tf32r(x.w); lo.w = tf32r(x.w - hi.w);
}
__device__ __forceinline__ void mma8(float* c, const unsigned* a, const unsigned* b) {
    asm volatile(
        "mma.sync.aligned.m16n8k8.row.col.f32.tf32.tf32.f32 "
        "{%0,%1,%2,%3}, {%4,%5,%6,%7}, {%8,%9}, {%0,%1,%2,%3};"
        : "+f"(c[0]), "+f"(c[1]), "+f"(c[2]), "+f"(c[3])
        : "r"(a[0]), "r"(a[1]), "r"(a[2]), "r"(a[3]), "r"(b[0]), "r"(b[1]));
}
#define LDSM4(r, addr)                                                         \
    asm volatile("ldmatrix.sync.aligned.m8n8.x4.shared.b16 {%0,%1,%2,%3}, [%4];"\
        : "=r"((r)[0]), "=r"((r)[1]), "=r"((r)[2]), "=r"((r)[3])               \
        : "r"(addr))

// ---------------------------------------------------------------------------
// ldmatrix fragment gather + 3-pass MMAs (256-thread version: warp grid 2x4,
// each warp 64(m) x 32(n): 4 A-fragments x 4 B-fragments).
// ---------------------------------------------------------------------------
#define FRAG_COMPUTE_L(stb, AL_B, BH_B, BL_B, NKS)                             \
    _Pragma("unroll")                                                          \
    for (int ks = 0; ks < (NKS); ks++) {                                       \
        const unsigned kb = (unsigned)(ks * 32);                               \
        unsigned Ah[4][4], Al[4][4], Bh[4][2], Bl[4][2];                       \
        _Pragma("unroll")                                                      \
        for (int f = 0; f < 4; f++) {                                          \
            LDSM4(Ah[f], (stb) + aoff[f] + kb);                                \
            LDSM4(Al[f], (stb) + (AL_B) + aoff[f] + kb);                       \
        }                                                                      \
        _Pragma("unroll")                                                      \
        for (int hh = 0; hh < 2; hh++) {                                       \
            unsigned tb[4];                                                    \
            LDSM4(tb, (stb) + (BH_B) + boff[hh] + kb);                         \
            Bh[2*hh][0] = tb[0]; Bh[2*hh][1] = tb[1];                          \
            Bh[2*hh+1][0] = tb[2]; Bh[2*hh+1][1] = tb[3];                      \
            LDSM4(tb, (stb) + (BL_B) + boff[hh] + kb);                         \
            Bl[2*hh][0] = tb[0]; Bl[2*hh][1] = tb[1];                          \
            Bl[2*hh+1][0] = tb[2]; Bl[2*hh+1][1] = tb[3];                      \
        }                                                                      \
        _Pragma("unroll")                                                      \
        for (int f = 0; f < 4; f++)                                            \
            _Pragma("unroll")                                                  \
            for (int h = 0; h < 4; h++)                                        \
                mma8(acc[f][h], Ah[f], Bh[h]);                                 \
        _Pragma("unroll")                                                      \
        for (int f = 0; f < 4; f++)                                            \
            _Pragma("unroll")                                                  \
            for (int h = 0; h < 4; h++)                                        \
                mma8(acc[f][h], Ah[f], Bl[h]);                                 \
        _Pragma("unroll")                                                      \
        for (int f = 0; f < 4; f++)                                            \
            _Pragma("unroll")                                                  \
            for (int h = 0; h < 4; h++)                                        \
                mma8(acc[f][h], Al[f], Bh[h]);                                 \
    }

// precompute ldmatrix offsets for pitch P (floats); needs lane, mw, nw
#define LDSM_OFFSETS(P)                                                        \
    const int aRow = lane & 15;                                                \
    const int aCol = (lane >> 4) << 2;                                         \
    const int bRow = ((lane >> 4) << 3) + (lane & 7);                          \
    const int bCol = ((lane >> 3) & 1) << 2;                                   \
    unsigned aoff[4], boff[2];                                                 \
    _Pragma("unroll")                                                          \
    for (int f = 0; f < 4; f++)                                                \
        aoff[f] = (unsigned)(((mw + f * 16 + aRow) * (P) + aCol) * 4);         \
    _Pragma("unroll")                                                          \
    for (int hh = 0; hh < 2; hh++)                                             \
        boff[hh] = (unsigned)(((nw + hh * 16 + bRow) * (P) + bCol) * 4);

// ===========================================================================
// mm_gemm: batched symmetric D = A x B^T on 3 upper 128x128 tiles + mirror.
// fp32 operands split at stage time, register-prefetch double buffering,
// ldmatrix gather, 256 threads.
// z<NB: (A1,B1,D1); z>=NB: (A2,B2,D2).
// epi 0: D=P
// epi 2: D=P*rsqrt(tr_now)
// epi 3: fused SICE: D(=L) = sice(L, Cn - P, dec)
// epi 4: axpy: D = 1.5*S - 0.5*P          (S = A-operand source)
// epi 5: axpy+scale: D = (1.5*S-0.5*P)*rsqrt(tr_now)
// Diagonal tiles write trace partials trp[b*2 + (tt==2)] when trp!=null.
// grid (3, 1, NB or 2NB), 256 threads, MM_SMEM dynamic smem.
// ===========================================================================
__global__ __launch_bounds__(256, 1) void mm_gemm(
    const float* __restrict__ A1, const float* __restrict__ B1, float* __restrict__ D1,
    const float* __restrict__ A2, const float* __restrict__ B2, float* __restrict__ D2,
    const float* __restrict__ tr_now, int epi, const float* __restrict__ Cn, float dec,
    float* __restrict__ trp)
{
    extern __shared__ float Sf[];
    const int z = blockIdx.z;
    const int b = z & (NB - 1);
    const float* Ab = ((z >= NB) ? A2 : A1) + (size_t)b * MAT;
    const float* Bb = ((z >= NB) ? B2 : B1) + (size_t)b * MAT;
    float* Dp = ((z >= NB) ? D2 : D1) + (size_t)b * MAT;
    const int tt = blockIdx.x;
    const int mi = (tt == 2) ? 1 : 0;
    const int nj = (tt == 0) ? 0 : 1;
    const int m0 = mi * 128, n0 = nj * 128;

    const int tid = threadIdx.x;
    const int wid = tid >> 5, lane = tid & 31;
    const int g = lane >> 2, t = lane & 3;
    const int wm = wid >> 2, wn = wid & 3;
    const int mw = wm * 64, nw = wn * 32;
    const int srow = tid >> 3, sq = tid & 7;
    const unsigned sb = smem_u32(Sf);
    LDSM_OFFSETS(36)

    float4 pa[4], pb[4];
    float acc[4][4][4] = {};

    #pragma unroll
    for (int p = 0; p < 4; p++) {
        const int row = srow + p * 32;
        pa[p] = *(const float4*)(Ab + (size_t)(m0 + row) * DD + sq * 4);
        pb[p] = *(const float4*)(Bb + (size_t)(n0 + row) * DD + sq * 4);
    }
    {
        float* sAh = Sf; float* sAl = Sf + 4608;
        float* sBh = Sf + 9216; float* sBl = Sf + 13824;
        #pragma unroll
        for (int p = 0; p < 4; p++) {
            const int row = srow + p * 32;
            float4 hi, lo;
            split4(pa[p], hi, lo);
            *(float4*)(sAh + row * 36 + sq * 4) = hi;
            *(float4*)(sAl + row * 36 + sq * 4) = lo;
            split4(pb[p], hi, lo);
            *(float4*)(sBh + row * 36 + sq * 4) = hi;
            *(float4*)(sBl + row * 36 + sq * 4) = lo;
        }
    }
    __syncthreads();

    for (int c = 0; c < 8; c++) {
        if (c < 7) {
            const int k0 = (c + 1) * 32;
            #pragma unroll
            for (int p = 0; p < 4; p++) {
                const int row = srow + p * 32;
                pa[p] = *(const float4*)(Ab + (size_t)(m0 + row) * DD + k0 + sq * 4);
                pb[p] = *(const float4*)(Bb + (size_t)(n0 + row) * DD + k0 + sq * 4);
            }
        }
        {
            const unsigned stb = sb + (unsigned)((c & 1) * STG * 4);
            FRAG_COMPUTE_L(stb, 18432u, 36864u, 55296u, 4)
        }
        if (c < 7) {
            float* base = Sf + ((c + 1) & 1) * STG;
            float* sAh = base; float* sAl = base + 4608;
            float* sBh = base + 9216; float* sBl = base + 13824;
            #pragma unroll
            for (int p = 0; p < 4; p++) {
                const int row = srow + p * 32;
                float4 hi, lo;
                split4(pa[p], hi, lo);
                *(float4*)(sAh + row * 36 + sq * 4) = hi;
                *(float4*)(sAl + row * 36 + sq * 4) = lo;
                split4(pb[p], hi, lo);
                *(float4*)(sBh + row * 36 + sq * 4) = hi;
                *(float4*)(sBl + row * 36 + sq * 4) = lo;
            }
            __syncthreads();
        }
    }

    // ---- epilogue ----
    const float rs = (epi == 2 || epi == 5) ? rsqrtf(tr_now[b]) : 1.0f;
    const float* Cb = (epi == 3) ? (Cn + (size_t)b * MAT) : nullptr;
    float dsum = 0.f;
    const bool mir  = (mi != nj);
    const bool diag = (trp != nullptr) && (mi == nj);
    #pragma unroll
    for (int f = 0; f < 4; f++) {
        const int r0 = m0 + mw + f * 16 + g;
        const int r1 = r0 + 8;
        #pragma unroll
        for (int h = 0; h < 4; h++) {
            const int c = n0 + nw + h * 8 + 2 * t;
            float v[4] = {acc[f][h][0], acc[f][h][1], acc[f][h][2], acc[f][h][3]};
            const int rr[4] = {r0, r0, r1, r1};
            const int cc[4] = {c, c + 1, c, c + 1};
            if (epi == 2) {
                #pragma unroll
                for (int j = 0; j < 4; j++) v[j] *= rs;
            } else if (epi == 3) {
                #pragma unroll
                for (int j = 0; j < 4; j++) {
                    float Lv = Dp[(size_t)rr[j] * DD + cc[j]];
                    float gg = Cb[(size_t)rr[j] * DD + cc[j]] - v[j];
                    v[j] = sice_f(Lv, gg, dec);
                }
            } else if (epi >= 4) {
                #pragma unroll
                for (int j = 0; j < 4; j++) {
                    float Sv = Ab[(size_t)rr[j] * DD + cc[j]];
                    v[j] = fmaf(-0.5f, v[j], 1.5f * Sv);
                    if (epi == 5) v[j] *= rs;
                }
            }
            if (diag) {
                #pragma unroll
                for (int j = 0; j < 4; j++)
                    if (rr[j] == cc[j]) dsum += v[j];
            }
            *(float2*)(Dp + (size_t)r0 * DD + c) = make_float2(v[0], v[1]);
            *(float2*)(Dp + (size_t)r1 * DD + c) = make_float2(v[2], v[3]);
            if (mir) {
                #pragma unroll
                for (int j = 0; j < 4; j++)
                    Dp[(size_t)cc[j] * DD + rr[j]] = v[j];
            }
        }
    }

    if (diag) {
        __syncthreads();
        Sf[tid] = dsum;
        __syncthreads();
        if (tid == 0) {
            float s2 = 0.f;
            for (int u = 0; u < 256; u++) s2 += Sf[u];
            trp[b * 2 + mi] = s2;
        }
    }
}

// ===========================================================================
// cov_mma (R12 verbatim): C[b] = (Y Y^T)/784 - mu mu^T, tf32 split-2 mma +
// ldmatrix, 3-tile symmetric grid with mirror. K=784 = 49 chunks of 16.
// grid (3, 1, NB), 256 threads, COV_SMEM dynamic smem. pitch 20.
// ===========================================================================
__global__ __launch_bounds__(256, 1) void cov_mma(
    const float* __restrict__ y, const float* __restrict__ rowmean,
    float* __restrict__ C)
{
    extern __shared__ float Sf[];
    const int b = blockIdx.z;
    const int tt = blockIdx.x;
    const int ti = (tt == 2) ? 1 : 0;
    const int tj = (tt == 0) ? 0 : 1;
    const int i0 = ti * 128, j0 = tj * 128;
    const float* Yb = y + (size_t)b * DD * MMs;

    const int tid = threadIdx.x;
    const int wid = tid >> 5, lane = tid & 31;
    const int g = lane >> 2, t = lane & 3;
    const int wm = wid >> 2, wn = wid & 3;
    const int mw = wm * 64, nw = wn * 32;
    const int srow = tid >> 1, q2 = tid & 1;
    const unsigned sb = smem_u32(Sf);
    LDSM_OFFSETS(20)

    float4 pya[2], pyb[2];
    float acc[4][4][4] = {};

    #pragma unroll
    for (int j = 0; j < 2; j++) {
        pya[j] = *(const float4*)(Yb + (size_t)(i0 + srow) * MMs + q2 * 8 + j * 4);
        pyb[j] = *(const float4*)(Yb + (size_t)(j0 + srow) * MMs + q2 * 8 + j * 4);
    }
    {
        float* sAh = Sf; float* sAl = Sf + 2560;
        float* sBh = Sf + 5120; float* sBl = Sf + 7680;
        #pragma unroll
        for (int j = 0; j < 2; j++) {
            float4 hi, lo;
            split4(pya[j], hi, lo);
            *(float4*)(sAh + srow * 20 + q2 * 8 + j * 4) = hi;
            *(float4*)(sAl + srow * 20 + q2 * 8 + j * 4) = lo;
            split4(pyb[j], hi, lo);
            *(float4*)(sBh + srow * 20 + q2 * 8 + j * 4) = hi;
            *(float4*)(sBl + srow * 20 + q2 * 8 + j * 4) = lo;
        }
    }
    __syncthreads();

    const int NCH = MMs / 16;   // 49
    for (int c = 0; c < NCH; c++) {
        if (c + 1 < NCH) {
            const int k0 = (c + 1) * 16;
            #pragma unroll
            for (int j = 0; j < 2; j++) {
                pya[j] = *(const float4*)(Yb + (size_t)(i0 + srow) * MMs + k0 + q2 * 8 + j * 4);
                pyb[j] = *(const float4*)(Yb + (size_t)(j0 + srow) * MMs + k0 + q2 * 8 + j * 4);
            }
        }
        {
            const unsigned stb = sb + (unsigned)((c & 1) * 40960);
            FRAG_COMPUTE_L(stb, 10240u, 20480u, 30720u, 2)
        }
        if (c + 1 < NCH) {
            float* base = Sf + ((c + 1) & 1) * 10240;
            float* sAh = base; float* sAl = base + 2560;
            float* sBh = base + 5120; float* sBl = base + 7680;
            #pragma unroll
            for (int j = 0; j < 2; j++) {
                float4 hi, lo;
                split4(pya[j], hi, lo);
                *(float4*)(sAh + srow * 20 + q2 * 8 + j * 4) = hi;
                *(float4*)(sAl + srow * 20 + q2 * 8 + j * 4) = lo;
                split4(pyb[j], hi, lo);
                *(float4*)(sBh + srow * 20 + q2 * 8 + j * 4) = hi;
                *(float4*)(sBl + srow * 20 + q2 * 8 + j * 4) = lo;
            }
            __syncthreads();
        }
    }

    const float invM = 1.0f / (float)MMs;
    const float* mu = rowmean + b * DD;
    float* Cb = C + (size_t)b * MAT;
    #pragma unroll
    for (int f = 0; f < 4; f++) {
        const int r0 = i0 + mw + f * 16 + g;
        const int r1 = r0 + 8;
        const float m0v = mu[r0], m1v = mu[r1];
        #pragma unroll
        for (int h = 0; h < 4; h++) {
            const int c = j0 + nw + h * 8 + 2 * t;
            const float mc0 = mu[c], mc1 = mu[c + 1];
            float v[4];
            v[0] = acc[f][h][0] * invM - m0v * mc0;
            v[1] = acc[f][h][1] * invM - m0v * mc1;
            v[2] = acc[f][h][2] * invM - m1v * mc0;
            v[3] = acc[f][h][3] * invM - m1v * mc1;
            *(float2*)(Cb + (size_t)r0 * DD + c) = make_float2(v[0], v[1]);
            *(float2*)(Cb + (size_t)r1 * DD + c) = make_float2(v[2], v[3]);
            if (ti != tj) {
                Cb[(size_t)c * DD + r0]       = v[0];
                Cb[(size_t)(c + 1) * DD + r0] = v[1];
                Cb[(size_t)c * DD + r1]       = v[2];
                Cb[(size_t)(c + 1) * DD + r1] = v[3];
            }
        }
    }
}

// ===========================================================================
// conv_mma (R12 verbatim): y[b] = w @ x[b], tf32 split-2 mma + ldmatrix.
// grid (7, 2, NB), 256 threads, pitch 36.
// ===========================================================================
__global__ __launch_bounds__(256, 1) void conv_mma(
    const float* __restrict__ x, const float* __restrict__ w, float* __restrict__ y)
{
    extern __shared__ float Sf[];
    const int b = blockIdx.z;
    const int mi = blockIdx.y, nj = blockIdx.x;
    const int m0 = mi * 128, n0 = nj * 128;
    const float* Bx = x + (size_t)b * CINc * MMs;
    float* Dp = y + (size_t)b * DD * MMs;

    const int tid = threadIdx.x;
    const int wid = tid >> 5, lane = tid & 31;
    const int g = lane >> 2, t = lane & 3;
    const int wm = wid >> 2, wn = wid & 3;
    const int mw = wm * 64, nw = wn * 32;
    const int srow = tid >> 3, sq = tid & 7;
    const int bn = tid & 127, bkh = tid >> 7;
    const bool bvalid = (n0 + bn) < MMs;
    const unsigned sb = smem_u32(Sf);
    LDSM_OFFSETS(36)

    float4 pa[4];
    float pbv[16];
    float acc[4][4][4] = {};

    #pragma unroll
    for (int p = 0; p < 4; p++) {
        const int row = srow + p * 32;
        pa[p] = *(const float4*)(w + (size_t)(m0 + row) * CINc + sq * 4);
    }
    #pragma unroll
    for (int q = 0; q < 16; q++) {
        const int kk = bkh * 16 + q;
        pbv[q] = bvalid ? Bx[(size_t)kk * MMs + n0 + bn] : 0.f;
    }
    {
        float* sAh = Sf; float* sAl = Sf + 4608;
        float* sBh = Sf + 9216; float* sBl = Sf + 13824;
        #pragma unroll
        for (int p = 0; p < 4; p++) {
            const int row = srow + p * 32;
            float4 hi, lo;
            split4(pa[p], hi, lo);
            *(float4*)(sAh + row * 36 + sq * 4) = hi;
            *(float4*)(sAl + row * 36 + sq * 4) = lo;
        }
        #pragma unroll
        for (int q4 = 0; q4 < 4; q4++) {
            float4 v = make_float4(pbv[q4*4], pbv[q4*4+1], pbv[q4*4+2], pbv[q4*4+3]);
            float4 hi, lo;
            split4(v, hi, lo);
            *(float4*)(sBh + bn * 36 + bkh * 16 + q4 * 4) = hi;
            *(float4*)(sBl + bn * 36 + bkh * 16 + q4 * 4) = lo;
        }
    }
    __syncthreads();

    const int NCH = CINc / 32;   // 64
    for (int c = 0; c < NCH; c++) {
        if (c + 1 < NCH) {
            const int k0 = (c + 1) * 32;
            #pragma unroll
            for (int p = 0; p < 4; p++) {
                const int row = srow + p * 32;
                pa[p] = *(const float4*)(w + (size_t)(m0 + row) * CINc + k0 + sq * 4);
            }
            #pragma unroll
            for (int q = 0; q < 16; q++) {
                const int kk = bkh * 16 + q;
                pbv[q] = bvalid ? Bx[(size_t)(k0 + kk) * MMs + n0 + bn] : 0.f;
            }
        }
        {
            const unsigned stb = sb + (unsigned)((c & 1) * STG * 4);
            FRAG_COMPUTE_L(stb, 18432u, 36864u, 55296u, 4)
        }
        if (c + 1 < NCH) {
            float* base = Sf + ((c + 1) & 1) * STG;
            float* sAh = base; float* sAl = base + 4608;
            float* sBh = base + 9216; float* sBl = base + 13824;
            #pragma unroll
            for (int p = 0; p < 4; p++) {
                const int row = srow + p * 32;
                float4 hi, lo;
                split4(pa[p], hi, lo);
                *(float4*)(sAh + row * 36 + sq * 4) = hi;
                *(float4*)(sAl + row * 36 + sq * 4) = lo;
            }
            #pragma unroll
            for (int q4 = 0; q4 < 4; q4++) {
                float4 v = make_float4(pbv[q4*4], pbv[q4*4+1], pbv[q4*4+2], pbv[q4*4+3]);
                float4 hi, lo;
                split4(v, hi, lo);
                *(float4*)(sBh + bn * 36 + bkh * 16 + q4 * 4) = hi;
                *(float4*)(sBl + bn * 36 + bkh * 16 + q4 * 4) = lo;
            }
            __syncthreads();
        }
    }

    #pragma unroll
    for (int f = 0; f < 4; f++) {
        const int r0 = m0 + mw + f * 16 + g;
        const int r1 = r0 + 8;
        #pragma unroll
        for (int h = 0; h < 4; h++) {
            const int c = n0 + nw + h * 8 + 2 * t;
            if (c < MMs) {
                *(float2*)(Dp + (size_t)r0 * MMs + c) =
                    make_float2(acc[f][h][0], acc[f][h][1]);
                *(float2*)(Dp + (size_t)r1 * MMs + c) =
                    make_float2(acc[f][h][2], acc[f][h][3]);
            }
        }
    }
}

// ===========================================================================
// BN kernels (unchanged)
// ===========================================================================
__global__ void bn_stats(const float* __restrict__ y, float* __restrict__ mean,
                         float* __restrict__ rstd)
{
    const int d = blockIdx.x;
    const int t = threadIdx.x;
    float s = 0.f, s2 = 0.f;
    for (int b = 0; b < NB; b++) {
        const float* p = y + (size_t)b * DD * MMs + (size_t)d * MMs;
        for (int m = t; m < MMs; m += 256) { float v = p[m]; s += v; s2 = fmaf(v, v, s2); }
    }
    __shared__ float sh1[8], sh2[8];
    const int lane = t & 31, wid = t >> 5;
    s = warpReduce(s); s2 = warpReduce(s2);
    if (lane == 0) { sh1[wid] = s; sh2[wid] = s2; }
    __syncthreads();
    if (wid == 0) {
        s  = (lane < 8) ? sh1[lane] : 0.f;
        s2 = (lane < 8) ? sh2[lane] : 0.f;
        s = warpReduce(s); s2 = warpReduce(s2);
        if (lane == 0) {
            const float N = (float)(NB * MMs);
            float mu  = s / N;
            float var = s2 / N - mu * mu;
            mean[d] = mu;
            rstd[d] = rsqrtf(var + 1e-5f);
        }
    }
}

__global__ void bn_apply(float* __restrict__ y, const float* __restrict__ mean,
                         const float* __restrict__ rstd, const float* __restrict__ gamma,
                         const float* __restrict__ beta, float* __restrict__ rowmean)
{
    const int bd = blockIdx.x;
    const int d  = bd & (DD - 1);
    float* p = y + (size_t)bd * MMs;
    const float mu = mean[d], rs = rstd[d], g = gamma[d], be = beta[d];
    const int t = threadIdx.x;
    float s = 0.f;
    for (int m = t; m < MMs; m += 256) {
        float v = fmaf((p[m] - mu) * rs, g, be);
        v = fmaxf(v, 0.f);
        p[m] = v;
        s += v;
    }
    __shared__ float sh[8];
    const int lane = t & 31, wid = t >> 5;
    s = warpReduce(s);
    if (lane == 0) sh[wid] = s;
    __syncthreads();
    if (wid == 0) {
        s = (lane < 8) ? sh[lane] : 0.f;
        s = warpReduce(s);
        if (lane == 0) rowmean[bd] = s * (1.0f / MMs);
    }
}

// ---------------------------------------------------------------------------
// small kernels
// ---------------------------------------------------------------------------
__global__ void tracek0(const float* __restrict__ X, const float* __restrict__ jitter,
                        float* __restrict__ tr0, float* __restrict__ jcp)
{
    const int b = blockIdx.x;
    const int t = threadIdx.x;
    float v = X[(size_t)b * MAT + t * 257];
    float jt = 1e-10f + 1e-9f * jitter[t];
    __shared__ float sh[8], shj[8];
    const int lane = t & 31, wid = t >> 5;
    v = warpReduce(v); jt = warpReduce(jt);
    if (lane == 0) { sh[wid] = v; shj[wid] = jt; }
    __syncthreads();
    if (wid == 0) {
        v  = (lane < 8) ? sh[lane]  : 0.f;
        jt = (lane < 8) ? shj[lane] : 0.f;
        v = warpReduce(v); jt = warpReduce(jt);
        if (lane == 0) {
            tr0[b] = v;
            if (b == 0) *jcp = jt;
        }
    }
}

__global__ void scalek(float* __restrict__ C, const float* __restrict__ tr0)
{
    const int idx = blockIdx.x * 256 + threadIdx.x;
    C[idx] *= (1.0f / tr0[idx >> 16]);
}

__global__ void prep_ns(const float* __restrict__ Sm, const float* __restrict__ jitter,
                        const float* __restrict__ trp, const float* __restrict__ jcp,
                        float* __restrict__ A, float* __restrict__ ZY,
                        float* __restrict__ tr_now)
{
    const int idx = blockIdx.x * 256 + threadIdx.x;
    const int b = idx >> 16, rc = idx & 65535, r = rc >> 8, c = rc & 255;
    const float jc = *jcp;
    float t;
    if (trp != nullptr) t = trp[b*2+0] + trp[b*2+1] + jc;
    else                t = 1.0f + jc;
    float v = Sm[idx];
    if (r == c) v += 1e-10f + 1e-9f * jitter[r];
    float a = v * (1.0f / t);
    A[idx] = a;
    ZY[idx] = (r == c ? 1.5f : 0.0f) - 0.5f * a;
    if (rc == 0) tr_now[b] = t;
}

__global__ void gather_out(const float* __restrict__ L, const float* __restrict__ trp,
                           float* __restrict__ out)
{
    const int b = blockIdx.y, i = blockIdx.x, j = threadIdx.x;
    if (j < i) return;
    const float t = trp[b*2+0] + trp[b*2+1];
    const float s = rsqrtf(t);
    const int k = i * 256 - (i * (i - 1)) / 2 + (j - i);
    out[(size_t)b * 32896 + k] = L[(size_t)b * MAT + i * 256 + j] * s;
}

// ---------------------------------------------------------------------------
// Host orchestration — M-form Newton-Schulz:
//   Y1 = A @ ZY0 ; Z1 = ZY0
//   loop 5x:  M = Z@Y ;  Y' = 1.5Y - 0.5 Y@M ;  Z' = 1.5Z - 0.5 Z@M
//   M = Z@Y ;  zz = (1.5Z - 0.5 Z@M) * rsqrt(t)
// ---------------------------------------------------------------------------
static void run_inv(const float* Sm, const float* jitter, const float* trp_in,
                    float* zz, float* tr_now, const float* jcp,
                    float* A, float* Y, float* Z, float* Y2, float* Z2, float* M)
{
    const dim3 g1(3, 1, NB);
    const dim3 g2(3, 1, 2 * NB);
    const float* FN = nullptr;
    float* FNm = nullptr;
    prep_ns<<<BMAT / 256, 256>>>(Sm, jitter, trp_in, jcp, A, Z, tr_now);   // Z = ZY0
    mm_gemm<<<g1, 256, MM_SMEM>>>(A, Z, Y, FN, FN, FNm, tr_now, 0, FN, 0.f, FNm);
    float *Yc = Y, *Zc = Z, *Ya = Y2, *Za = Z2;
    for (int it = 0; it < 5; it++) {
        mm_gemm<<<g1, 256, MM_SMEM>>>(Zc, Yc, M, FN, FN, FNm, tr_now, 0, FN, 0.f, FNm);
        // pair: Ya = 1.5*Yc - 0.5*Yc@M ; Za = 1.5*Zc - 0.5*Zc@M
        mm_gemm<<<g2, 256, MM_SMEM>>>(Yc, M, Ya, Zc, M, Za, tr_now, 4, FN, 0.f, FNm);
        float* t1 = Yc; Yc = Ya; Ya = t1;
        float* t2 = Zc; Zc = Za; Za = t2;
    }
    mm_gemm<<<g1, 256, MM_SMEM>>>(Zc, Yc, M, FN, FN, FNm, tr_now, 0, FN, 0.f, FNm);
    // zz = (1.5*Zc - 0.5*Zc@M) * rsqrt(tr_now)
    mm_gemm<<<g1, 256, MM_SMEM>>>(Zc, M, zz, FN, FN, FNm, tr_now, 5, FN, 0.f, FNm);
}

extern "C" void kernel_launch(void* const* d_in, const int* in_sizes, int n_in,
                              void* d_out, int out_size)
{
    (void)in_sizes; (void)n_in; (void)out_size;
    const float* x      = (const float*)d_in[0];
    const float* w      = (const float*)d_in[1];
    const float* gamma  = (const float*)d_in[2];
    const float* beta   = (const float*)d_in[3];
    const float* jitter = (const float*)d_in[4];
    float* out = (float*)d_out;

    cudaFuncSetAttribute(mm_gemm, cudaFuncAttributeMaxDynamicSharedMemorySize, MM_SMEM);
    cudaFuncSetAttribute(conv_mma, cudaFuncAttributeMaxDynamicSharedMemorySize, MM_SMEM);
    cudaFuncSetAttribute(cov_mma, cudaFuncAttributeMaxDynamicSharedMemorySize, COV_SMEM);

    float *y, *mats, *small;
    cudaGetSymbolAddress((void**)&y, g_y);
    cudaGetSymbolAddress((void**)&mats, g_mats);
    cudaGetSymbolAddress((void**)&small, g_small);

    float* Cn  = mats + 0u * BMAT;
    float* A   = mats + 1u * BMAT;
    float* Y   = mats + 2u * BMAT;
    float* Z   = mats + 3u * BMAT;
    float* Y2  = mats + 4u * BMAT;
    float* Z2  = mats + 5u * BMAT;
    float* M   = mats + 6u * BMAT;
    float* zz  = mats + 7u * BMAT;
    float* LLT = mats + 8u * BMAT;

    float* bn_mean = small;
    float* bn_rstd = small + 256;
    float* rowmean = small + 512;
    float* tr0     = small + 8704;
    float* tr_now  = small + 8736;
    float* jcp     = small + 8768;
    float* trp     = small + 8772;

    const dim3 g1(3, 1, NB);
    const float* FN = nullptr;
    float* FNm = nullptr;

    // Stage 1: conv (tensor) + BN + ReLU
    conv_mma<<<dim3(7, 2, NB), 256, MM_SMEM>>>(x, w, y);
    bn_stats<<<DD, 256>>>(y, bn_mean, bn_rstd);
    bn_apply<<<NB * DD, 256>>>(y, bn_mean, bn_rstd, gamma, beta, rowmean);

    // Stage 2: covariance (tensor) + trace normalize
    cov_mma<<<dim3(3, 1, NB), 256, COV_SMEM>>>(y, rowmean, Cn);
    tracek0<<<NB, 256>>>(Cn, jitter, tr0, jcp);
    scalek<<<BMAT / 256, 256>>>(Cn, tr0);

    // Stage 3: LLT = inv_sqrtm(Cn + Ij)^2 ; tr(Cn+Ij) = 1 + jc analytically
    run_inv(Cn, jitter, nullptr, zz, tr_now, jcp, A, Y, Z, Y2, Z2, M);
    mm_gemm<<<g1, 256, MM_SMEM>>>(zz, zz, LLT, FN, FN, FNm, tr_now, 0, FN, 0.f, trp);

    // Stage 4: SICE loop (i=2 has dec==0 -> exact identity, skipped)
    for (int i = 0; i < 2; i++) {
        run_inv(LLT, jitter, trp, zz, tr_now, jcp, A, Y, Z, Y2, Z2, M);
        const float dec = 5.0f * (1.0f - (float)i / 2.0f);
        mm_gemm<<<g1, 256, MM_SMEM>>>(zz, zz, LLT, FN, FN, FNm, tr_now, 3, Cn, dec, trp);
    }

    // Stage 5: triuvec with trace from final epi3 partials
    gather_out<<<dim3(DD, NB), 256>>>(LLT, trp, out);
}

// round 16
// speedup vs baseline: 1.0881x; 1.0881x over previous
#include <cuda_runtime.h>

#define NB   32
#define DD   256
#define MMs  784
#define CINc 2048
#define MAT  (DD*DD)          // 65536
#define BMAT (NB*MAT)         // 2,097,152
#define STG  18432            // floats per mma stage (4 arrays of 4608)
#define MM_SMEM 147456        // 2 stages * 18432 floats * 4B
#define COV_SMEM 81920        // 2 stages * 10240 floats * 4B
#define NPART 224             // 32 b * 7 n-chunks

// Scratch (device globals; no allocation anywhere)
__device__ float g_y[NB*DD*MMs];      // raw conv output [b][d][m]
__device__ float g_mats[9u*BMAT];     // 9 batched 256x256 buffers
__device__ float g_small[16384];
// [0,256) bn_mean [256,512) bn_rstd
// [8704,8736) tr0 [8736,8768) tr_now [8768] jc [8772,8836) trp (NB*2)

// ---------------------------------------------------------------------------
__device__ __forceinline__ float warpReduce(float v) {
    #pragma unroll
    for (int o = 16; o; o >>= 1) v += __shfl_down_sync(0xffffffffu, v, o);
    return v;
}

__device__ __forceinline__ float sice_f(float L, float g12, float dec)
{
    float lp = fmaxf(L, 0.f);
    float lm = fmaxf(-L, 0.f);
    lp = fmaxf(lp - dec * (g12 + 0.07f), 0.f);
    lm = fmaxf(lm - dec * (-g12 + 0.07f), 0.f);
    return lp - lm;
}

__device__ __forceinline__ unsigned smem_u32(const void* p) {
    unsigned a;
    asm("{ .reg .u64 t; cvta.to.shared.u64 t, %1; cvt.u32.u64 %0, t; }"
        : "=r"(a) : "l"(p));
    return a;
}

// ---------------------------------------------------------------------------
// tf32 helpers
// ---------------------------------------------------------------------------
__device__ __forceinline__ float tf32r(float x) {
    unsigned u;
    asm("cvt.rna.tf32.f32 %0, %1;" : "=r"(u) : "f"(x));
    return __uint_as_float(u);
}
__device__ __forceinline__ void split4(float4 x, float4& hi, float4& lo) {
    hi.x = tf32r(x.x); lo.x = tf32r(x.x - hi.x);
    hi.y = tf32r(x.y); lo.y = tf32r(x.y - hi.y);
    hi.z = tf32r(x.z); lo.z = tf32r(x.z - hi.z);
    hi.w = tf32r(x.w); lo.w = tf32r(x.w - hi.w);
}
__device__ __forceinline__ void mma8(float* c, const unsigned* a, const unsigned* b) {
    asm volatile(
        "mma.sync.aligned.m16n8k8.row.col.f32.tf32.tf32.f32 "
        "{%0,%1,%2,%3}, {%4,%5,%6,%7}, {%8,%9}, {%0,%1,%2,%3};"
        : "+f"(c[0]), "+f"(c[1]), "+f"(c[2]), "+f"(c[3])
        : "r"(a[0]), "r"(a[1]), "r"(a[2]), "r"(a[3]), "r"(b[0]), "r"(b[1]));
}
#define LDSM4(r, addr)                                                         \
    asm volatile("ldmatrix.sync.aligned.m8n8.x4.shared.b16 {%0,%1,%2,%3}, [%4];"\
        : "=r"((r)[0]), "=r"((r)[1]), "=r"((r)[2]), "=r"((r)[3])               \
        : "r"(addr))

// BN+ReLU a float4 with row params, accumulating the sum
__device__ __forceinline__ float4 bnrelu4(float4 x, float mu, float rs,
                                          float gm, float be, float& s) {
    float4 r;
    r.x = fmaxf(fmaf((x.x - mu) * rs, gm, be), 0.f);
    r.y = fmaxf(fmaf((x.y - mu) * rs, gm, be), 0.f);
    r.z = fmaxf(fmaf((x.z - mu) * rs, gm, be), 0.f);
    r.w = fmaxf(fmaf((x.w - mu) * rs, gm, be), 0.f);
    s += (r.x + r.y) + (r.z + r.w);
    return r;
}

// ---------------------------------------------------------------------------
// ldmatrix fragment gather + 3-pass MMAs (256 threads: warp grid 2x4,
// each warp 64(m) x 32(n): 4 A-fragments x 4 B-fragments).
// ---------------------------------------------------------------------------
#define FRAG_COMPUTE_L(stb, AL_B, BH_B, BL_B, NKS)                             \
    _Pragma("unroll")                                                          \
    for (int ks = 0; ks < (NKS); ks++) {                                       \
        const unsigned kb = (unsigned)(ks * 32);                               \
        unsigned Ah[4][4], Al[4][4], Bh[4][2], Bl[4][2];                       \
        _Pragma("unroll")                                                      \
        for (int f = 0; f < 4; f++) {                                          \
            LDSM4(Ah[f], (stb) + aoff[f] + kb);                                \
            LDSM4(Al[f], (stb) + (AL_B) + aoff[f] + kb);                       \
        }                                                                      \
        _Pragma("unroll")                                                      \
        for (int hh = 0; hh < 2; hh++) {                                       \
            unsigned tb[4];                                                    \
            LDSM4(tb, (stb) + (BH_B) + boff[hh] + kb);                         \
            Bh[2*hh][0] = tb[0]; Bh[2*hh][1] = tb[1];                          \
            Bh[2*hh+1][0] = tb[2]; Bh[2*hh+1][1] = tb[3];                      \
            LDSM4(tb, (stb) + (BL_B) + boff[hh] + kb);                         \
            Bl[2*hh][0] = tb[0]; Bl[2*hh][1] = tb[1];                          \
            Bl[2*hh+1][0] = tb[2]; Bl[2*hh+1][1] = tb[3];                      \
        }                                                                      \
        _Pragma("unroll")                                                      \
        for (int f = 0; f < 4; f++)                                            \
            _Pragma("unroll")                                                  \
            for (int h = 0; h < 4; h++)                                        \
                mma8(acc[f][h], Ah[f], Bh[h]);                                 \
        _Pragma("unroll")                                                      \
        for (int f = 0; f < 4; f++)                                            \
            _Pragma("unroll")                                                  \
            for (int h = 0; h < 4; h++)                                        \
                mma8(acc[f][h], Ah[f], Bl[h]);                                 \
        _Pragma("unroll")                                                      \
        for (int f = 0; f < 4; f++)                                            \
            _Pragma("unroll")                                                  \
            for (int h = 0; h < 4; h++)                                        \
                mma8(acc[f][h], Al[f], Bh[h]);                                 \
    }

// precompute ldmatrix offsets for pitch P (floats); needs lane, mw, nw
#define LDSM_OFFSETS(P)                                                        \
    const int aRow = lane & 15;                                                \
    const int aCol = (lane >> 4) << 2;                                         \
    const int bRow = ((lane >> 4) << 3) + (lane & 7);                          \
    const int bCol = ((lane >> 3) & 1) << 2;                                   \
    unsigned aoff[4], boff[2];                                                 \
    _Pragma("unroll")                                                          \
    for (int f = 0; f < 4; f++)                                                \
        aoff[f] = (unsigned)(((mw + f * 16 + aRow) * (P) + aCol) * 4);         \
    _Pragma("unroll")                                                          \
    for (int hh = 0; hh < 2; hh++)                                             \
        boff[hh] = (unsigned)(((nw + hh * 16 + bRow) * (P) + bCol) * 4);

// ===========================================================================
// mm_gemm (R12 exact): batched D(128x128 tile) = A x B^T.
// z<NB: (A1,B1,D1); z>=NB: (A2,B2,D2).
// epi 0: D=P; 1: D=1.5I-0.5P; 2: D=P*rsqrt(tr_now); 3: fused SICE on D(=L).
// Diagonal tiles (mi==nj) write trace partials trp[b*2+mi] when trp!=null.
// grid (2, 2, NB or 2NB), 256 threads, MM_SMEM dynamic smem.
// ===========================================================================
__global__ __launch_bounds__(256, 1) void mm_gemm(
    const float* __restrict__ A1, const float* __restrict__ B1, float* __restrict__ D1,
    const float* __restrict__ A2, const float* __restrict__ B2, float* __restrict__ D2,
    const float* __restrict__ tr_now, int epi, const float* __restrict__ Cn, float dec,
    float* __restrict__ trp)
{
    extern __shared__ float Sf[];
    const int z = blockIdx.z;
    const int b = z & (NB - 1);
    const float* Ab = ((z >= NB) ? A2 : A1) + (size_t)b * MAT;
    const float* Bb = ((z >= NB) ? B2 : B1) + (size_t)b * MAT;
    float* Dp = ((z >= NB) ? D2 : D1) + (size_t)b * MAT;
    const int mi = blockIdx.y, nj = blockIdx.x;
    const int m0 = mi * 128, n0 = nj * 128;

    const int tid = threadIdx.x;
    const int wid = tid >> 5, lane = tid & 31;
    const int g = lane >> 2, t = lane & 3;
    const int wm = wid >> 2, wn = wid & 3;
    const int mw = wm * 64, nw = wn * 32;
    const int srow = tid >> 3, sq = tid & 7;
    const unsigned sb = smem_u32(Sf);
    LDSM_OFFSETS(36)

    float4 pa[4], pb[4];
    float acc[4][4][4] = {};

    #pragma unroll
    for (int p = 0; p < 4; p++) {
        const int row = srow + p * 32;
        pa[p] = *(const float4*)(Ab + (size_t)(m0 + row) * DD + sq * 4);
        pb[p] = *(const float4*)(Bb + (size_t)(n0 + row) * DD + sq * 4);
    }
    {
        float* sAh = Sf; float* sAl = Sf + 4608;
        float* sBh = Sf + 9216; float* sBl = Sf + 13824;
        #pragma unroll
        for (int p = 0; p < 4; p++) {
            const int row = srow + p * 32;
            float4 hi, lo;
            split4(pa[p], hi, lo);
            *(float4*)(sAh + row * 36 + sq * 4) = hi;
            *(float4*)(sAl + row * 36 + sq * 4) = lo;
            split4(pb[p], hi, lo);
            *(float4*)(sBh + row * 36 + sq * 4) = hi;
            *(float4*)(sBl + row * 36 + sq * 4) = lo;
        }
    }
    __syncthreads();

    for (int c = 0; c < 8; c++) {
        if (c < 7) {
            const int k0 = (c + 1) * 32;
            #pragma unroll
            for (int p = 0; p < 4; p++) {
                const int row = srow + p * 32;
                pa[p] = *(const float4*)(Ab + (size_t)(m0 + row) * DD + k0 + sq * 4);
                pb[p] = *(const float4*)(Bb + (size_t)(n0 + row) * DD + k0 + sq * 4);
            }
        }
        {
            const unsigned stb = sb + (unsigned)((c & 1) * STG * 4);
            FRAG_COMPUTE_L(stb, 18432u, 36864u, 55296u, 4)
        }
        if (c < 7) {
            float* base = Sf + ((c + 1) & 1) * STG;
            float* sAh = base; float* sAl = base + 4608;
            float* sBh = base + 9216; float* sBl = base + 13824;
            #pragma unroll
            for (int p = 0; p < 4; p++) {
                const int row = srow + p * 32;
                float4 hi, lo;
                split4(pa[p], hi, lo);
                *(float4*)(sAh + row * 36 + sq * 4) = hi;
                *(float4*)(sAl + row * 36 + sq * 4) = lo;
                split4(pb[p], hi, lo);
                *(float4*)(sBh + row * 36 + sq * 4) = hi;
                *(float4*)(sBl + row * 36 + sq * 4) = lo;
            }
            __syncthreads();
        }
    }

    // ---- epilogue ----
    const float rs = (epi == 2) ? rsqrtf(tr_now[b]) : 1.0f;
    const float* Cb = (epi == 3) ? (Cn + (size_t)b * MAT) : nullptr;
    float dsum = 0.f;
    const bool diag = (trp != nullptr) && (mi == nj);
    #pragma unroll
    for (int f = 0; f < 4; f++) {
        const int r0 = m0 + mw + f * 16 + g;
        const int r1 = r0 + 8;
        #pragma unroll
        for (int h = 0; h < 4; h++) {
            const int c = n0 + nw + h * 8 + 2 * t;
            float v[4] = {acc[f][h][0], acc[f][h][1], acc[f][h][2], acc[f][h][3]};
            const int rr[4] = {r0, r0, r1, r1};
            const int cc[4] = {c, c + 1, c, c + 1};
            if (epi == 1) {
                #pragma unroll
                for (int j = 0; j < 4; j++)
                    v[j] = ((rr[j] == cc[j]) ? 1.5f : 0.0f) - 0.5f * v[j];
            } else if (epi == 2) {
                #pragma unroll
                for (int j = 0; j < 4; j++) v[j] *= rs;
            } else if (epi == 3) {
                #pragma unroll
                for (int j = 0; j < 4; j++) {
                    float Lv = Dp[(size_t)rr[j] * DD + cc[j]];
                    float gg = Cb[(size_t)rr[j] * DD + cc[j]] - v[j];
                    v[j] = sice_f(Lv, gg, dec);
                }
            }
            if (diag) {
                #pragma unroll
                for (int j = 0; j < 4; j++)
                    if (rr[j] == cc[j]) dsum += v[j];
            }
            *(float2*)(Dp + (size_t)r0 * DD + c) = make_float2(v[0], v[1]);
            *(float2*)(Dp + (size_t)r1 * DD + c) = make_float2(v[2], v[3]);
        }
    }

    if (diag) {
        __syncthreads();
        Sf[tid] = dsum;
        __syncthreads();
        if (tid == 0) {
            float s2 = 0.f;
            for (int u = 0; u < 256; u++) s2 += Sf[u];
            trp[b * 2 + mi] = s2;
        }
    }
}

// ===========================================================================
// cov_mma (BN-fused): reads RAW y, applies BN+ReLU in staging, accumulates
// per-row sums in-block; C[b] = (Yt Yt^T)/784 - mu mu^T.
// 3-tile symmetric grid with mirror. K=784 = 49 chunks of 16. pitch 20.
// grid (3, 1, NB), 256 threads, COV_SMEM dynamic smem.
// ===========================================================================
__global__ __launch_bounds__(256, 1) void cov_mma(
    const float* __restrict__ y,
    const float* __restrict__ bmean, const float* __restrict__ brstd,
    const float* __restrict__ gamma, const float* __restrict__ beta,
    float* __restrict__ C)
{
    extern __shared__ float Sf[];
    const int b = blockIdx.z;
    const int tt = blockIdx.x;
    const int ti = (tt == 2) ? 1 : 0;
    const int tj = (tt == 0) ? 0 : 1;
    const int i0 = ti * 128, j0 = tj * 128;
    const float* Yb = y + (size_t)b * DD * MMs;

    const int tid = threadIdx.x;
    const int wid = tid >> 5, lane = tid & 31;
    const int g = lane >> 2, t = lane & 3;
    const int wm = wid >> 2, wn = wid & 3;
    const int mw = wm * 64, nw = wn * 32;
    const int srow = tid >> 1, q2 = tid & 1;
    const unsigned sb = smem_u32(Sf);
    LDSM_OFFSETS(20)

    // per-row BN params (row = channel)
    const int chA = i0 + srow, chB = j0 + srow;
    const float muA = bmean[chA], rsA = brstd[chA], gA = gamma[chA], beA = beta[chA];
    const float muB = bmean[chB], rsB = brstd[chB], gB = gamma[chB], beB = beta[chB];
    float sumA = 0.f, sumB = 0.f;

    float4 pya[2], pyb[2];
    float acc[4][4][4] = {};

    #pragma unroll
    for (int j = 0; j < 2; j++) {
        pya[j] = *(const float4*)(Yb + (size_t)chA * MMs + q2 * 8 + j * 4);
        pyb[j] = *(const float4*)(Yb + (size_t)chB * MMs + q2 * 8 + j * 4);
    }
    {
        float* sAh = Sf; float* sAl = Sf + 2560;
        float* sBh = Sf + 5120; float* sBl = Sf + 7680;
        #pragma unroll
        for (int j = 0; j < 2; j++) {
            float4 hi, lo;
            float4 va = bnrelu4(pya[j], muA, rsA, gA, beA, sumA);
            split4(va, hi, lo);
            *(float4*)(sAh + srow * 20 + q2 * 8 + j * 4) = hi;
            *(float4*)(sAl + srow * 20 + q2 * 8 + j * 4) = lo;
            float4 vb = bnrelu4(pyb[j], muB, rsB, gB, beB, sumB);
            split4(vb, hi, lo);
            *(float4*)(sBh + srow * 20 + q2 * 8 + j * 4) = hi;
            *(float4*)(sBl + srow * 20 + q2 * 8 + j * 4) = lo;
        }
    }
    __syncthreads();

    const int NCH = MMs / 16;   // 49
    for (int c = 0; c < NCH; c++) {
        if (c + 1 < NCH) {
            const int k0 = (c + 1) * 16;
            #pragma unroll
            for (int j = 0; j < 2; j++) {
                pya[j] = *(const float4*)(Yb + (size_t)chA * MMs + k0 + q2 * 8 + j * 4);
                pyb[j] = *(const float4*)(Yb + (size_t)chB * MMs + k0 + q2 * 8 + j * 4);
            }
        }
        {
            const unsigned stb = sb + (unsigned)((c & 1) * 40960);
            FRAG_COMPUTE_L(stb, 10240u, 20480u, 30720u, 2)
        }
        if (c + 1 < NCH) {
            float* base = Sf + ((c + 1) & 1) * 10240;
            float* sAh = base; float* sAl = base + 2560;
            float* sBh = base + 5120; float* sBl = base + 7680;
            #pragma unroll
            for (int j = 0; j < 2; j++) {
                float4 hi, lo;
                float4 va = bnrelu4(pya[j], muA, rsA, gA, beA, sumA);
                split4(va, hi, lo);
                *(float4*)(sAh + srow * 20 + q2 * 8 + j * 4) = hi;
                *(float4*)(sAl + srow * 20 + q2 * 8 + j * 4) = lo;
                float4 vb = bnrelu4(pyb[j], muB, rsB, gB, beB, sumB);
                split4(vb, hi, lo);
                *(float4*)(sBh + srow * 20 + q2 * 8 + j * 4) = hi;
                *(float4*)(sBl + srow * 20 + q2 * 8 + j * 4) = lo;
            }
            __syncthreads();
        }
    }

    // publish row sums (stage-0 smem is free after last compute)
    __syncthreads();
    Sf[srow * 2 + q2]       = sumA;
    Sf[256 + srow * 2 + q2] = sumB;
    __syncthreads();

    const float invM = 1.0f / (float)MMs;
    float* Cb = C + (size_t)b * MAT;
    #pragma unroll
    for (int f = 0; f < 4; f++) {
        const int rl0 = mw + f * 16 + g;
        const int rl1 = rl0 + 8;
        const int r0 = i0 + rl0, r1 = i0 + rl1;
        const float m0v = (Sf[rl0 * 2] + Sf[rl0 * 2 + 1]) * invM;
        const float m1v = (Sf[rl1 * 2] + Sf[rl1 * 2 + 1]) * invM;
        #pragma unroll
        for (int h = 0; h < 4; h++) {
            const int cl = nw + h * 8 + 2 * t;
            const int c = j0 + cl;
            const float mc0 = (Sf[256 + cl * 2] + Sf[256 + cl * 2 + 1]) * invM;
            const float mc1 = (Sf[256 + cl * 2 + 2] + Sf[256 + cl * 2 + 3]) * invM;
            float v[4];
            v[0] = acc[f][h][0] * invM - m0v * mc0;
            v[1] = acc[f][h][1] * invM - m0v * mc1;
            v[2] = acc[f][h][2] * invM - m1v * mc0;
            v[3] = acc[f][h][3] * invM - m1v * mc1;
            *(float2*)(Cb + (size_t)r0 * DD + c) = make_float2(v[0], v[1]);
            *(float2*)(Cb + (size_t)r1 * DD + c) = make_float2(v[2], v[3]);
            if (ti != tj) {
                Cb[(size_t)c * DD + r0]       = v[0];
                Cb[(size_t)(c + 1) * DD + r0] = v[1];
                Cb[(size_t)c * DD + r1]       = v[2];
                Cb[(size_t)(c + 1) * DD + r1] = v[3];
            }
        }
    }
}

// ===========================================================================
// conv_mma (R12 + fused BN stat partials): y[b] = w @ x[b].
// Writes per-(channel, block) sum/sumsq partials: pS/pQ [256][NPART].
// grid (7, 2, NB), 256 threads, pitch 36.
// ===========================================================================
__global__ __launch_bounds__(256, 1) void conv_mma(
    const float* __restrict__ x, const float* __restrict__ w, float* __restrict__ y,
    float* __restrict__ pS, float* __restrict__ pQ)
{
    extern __shared__ float Sf[];
    const int b = blockIdx.z;
    const int mi = blockIdx.y, nj = blockIdx.x;
    const int m0 = mi * 128, n0 = nj * 128;
    const float* Bx = x + (size_t)b * CINc * MMs;
    float* Dp = y + (size_t)b * DD * MMs;

    const int tid = threadIdx.x;
    const int wid = tid >> 5, lane = tid & 31;
    const int g = lane >> 2, t = lane & 3;
    const int wm = wid >> 2, wn = wid & 3;
    const int mw = wm * 64, nw = wn * 32;
    const int srow = tid >> 3, sq = tid & 7;
    const int bn = tid & 127, bkh = tid >> 7;
    const bool bvalid = (n0 + bn) < MMs;
    const unsigned sb = smem_u32(Sf);
    LDSM_OFFSETS(36)

    float4 pa[4];
    float pbv[16];
    float acc[4][4][4] = {};

    #pragma unroll
    for (int p = 0; p < 4; p++) {
        const int row = srow + p * 32;
        pa[p] = *(const float4*)(w + (size_t)(m0 + row) * CINc + sq * 4);
    }
    #pragma unroll
    for (int q = 0; q < 16; q++) {
        const int kk = bkh * 16 + q;
        pbv[q] = bvalid ? Bx[(size_t)kk * MMs + n0 + bn] : 0.f;
    }
    {
        float* sAh = Sf; float* sAl = Sf + 4608;
        float* sBh = Sf + 9216; float* sBl = Sf + 13824;
        #pragma unroll
        for (int p = 0; p < 4; p++) {
            const int row = srow + p * 32;
            float4 hi, lo;
            split4(pa[p], hi, lo);
            *(float4*)(sAh + row * 36 + sq * 4) = hi;
            *(float4*)(sAl + row * 36 + sq * 4) = lo;
        }
        #pragma unroll
        for (int q4 = 0; q4 < 4; q4++) {
            float4 v = make_float4(pbv[q4*4], pbv[q4*4+1], pbv[q4*4+2], pbv[q4*4+3]);
            float4 hi, lo;
            split4(v, hi, lo);
            *(float4*)(sBh + bn * 36 + bkh * 16 + q4 * 4) = hi;
            *(float4*)(sBl + bn * 36 + bkh * 16 + q4 * 4) = lo;
        }
    }
    __syncthreads();

    const int NCH = CINc / 32;   // 64
    for (int c = 0; c < NCH; c++) {
        if (c + 1 < NCH) {
            const int k0 = (c + 1) * 32;
            #pragma unroll
            for (int p = 0; p < 4; p++) {
                const int row = srow + p * 32;
                pa[p] = *(const float4*)(w + (size_t)(m0 + row) * CINc + k0 + sq * 4);
            }
            #pragma unroll
            for (int q = 0; q < 16; q++) {
                const int kk = bkh * 16 + q;
                pbv[q] = bvalid ? Bx[(size_t)(k0 + kk) * MMs + n0 + bn] : 0.f;
            }
        }
        {
            const unsigned stb = sb + (unsigned)((c & 1) * STG * 4);
            FRAG_COMPUTE_L(stb, 18432u, 36864u, 55296u, 4)
        }
        if (c + 1 < NCH) {
            float* base = Sf + ((c + 1) & 1) * STG;
            float* sAh = base; float* sAl = base + 4608;
            float* sBh = base + 9216; float* sBl = base + 13824;
            #pragma unroll
            for (int p = 0; p < 4; p++) {
                const int row = srow + p * 32;
                float4 hi, lo;
                split4(pa[p], hi, lo);
                *(float4*)(sAh + row * 36 + sq * 4) = hi;
                *(float4*)(sAl + row * 36 + sq * 4) = lo;
            }
            #pragma unroll
            for (int q4 = 0; q4 < 4; q4++) {
                float4 v = make_float4(pbv[q4*4], pbv[q4*4+1], pbv[q4*4+2], pbv[q4*4+3]);
                float4 hi, lo;
                split4(v, hi, lo);
                *(float4*)(sBh + bn * 36 + bkh * 16 + q4 * 4) = hi;
                *(float4*)(sBl + bn * 36 + bkh * 16 + q4 * 4) = lo;
            }
            __syncthreads();
        }
    }

    // ---- store y + BN stat partials ----
    float rowS[8] = {}, rowQ[8] = {};
    #pragma unroll
    for (int f = 0; f < 4; f++) {
        const int r0 = m0 + mw + f * 16 + g;
        const int r1 = r0 + 8;
        #pragma unroll
        for (int h = 0; h < 4; h++) {
            const int c = n0 + nw + h * 8 + 2 * t;
            float a0 = acc[f][h][0], a1 = acc[f][h][1];
            float a2 = acc[f][h][2], a3 = acc[f][h][3];
            rowS[f*2]   += a0 + a1;  rowQ[f*2]   += a0*a0 + a1*a1;
            rowS[f*2+1] += a2 + a3;  rowQ[f*2+1] += a2*a2 + a3*a3;
            if (c < MMs) {
                *(float2*)(Dp + (size_t)r0 * MMs + c) = make_float2(a0, a1);
                *(float2*)(Dp + (size_t)r1 * MMs + c) = make_float2(a2, a3);
            }
        }
    }
    #pragma unroll
    for (int j = 0; j < 8; j++) {
        rowS[j] += __shfl_xor_sync(0xffffffffu, rowS[j], 1);
        rowS[j] += __shfl_xor_sync(0xffffffffu, rowS[j], 2);
        rowQ[j] += __shfl_xor_sync(0xffffffffu, rowQ[j], 1);
        rowQ[j] += __shfl_xor_sync(0xffffffffu, rowQ[j], 2);
    }
    __syncthreads();            // stage smem free
    float* sS = Sf;             // [128][4]
    float* sQ = Sf + 512;
    if (t == 0) {
        #pragma unroll
        for (int f = 0; f < 4; f++) {
            const int rl0 = mw + f * 16 + g, rl1 = rl0 + 8;
            sS[rl0 * 4 + wn] = rowS[f*2];   sQ[rl0 * 4 + wn] = rowQ[f*2];
            sS[rl1 * 4 + wn] = rowS[f*2+1]; sQ[rl1 * 4 + wn] = rowQ[f*2+1];
        }
    }
    __syncthreads();
    if (tid < 128) {
        float s = (sS[tid*4] + sS[tid*4+1]) + (sS[tid*4+2] + sS[tid*4+3]);
        float q = (sQ[tid*4] + sQ[tid*4+1]) + (sQ[tid*4+2] + sQ[tid*4+3]);
        const int ch = m0 + tid;
        pS[(size_t)ch * NPART + b * 7 + nj] = s;
        pQ[(size_t)ch * NPART + b * 7 + nj] = q;
    }
}

// ===========================================================================
// bn_reduce: per-channel stats from conv partials. grid 256, 256 threads.
// ===========================================================================
__global__ void bn_reduce(const float* __restrict__ pS, const float* __restrict__ pQ,
                          float* __restrict__ mean, float* __restrict__ rstd)
{
    const int ch = blockIdx.x;
    const int t = threadIdx.x;
    float s = 0.f, q = 0.f;
    if (t < NPART) {
        s = pS[(size_t)ch * NPART + t];
        q = pQ[(size_t)ch * NPART + t];
    }
    __shared__ float sh1[8], sh2[8];
    const int lane = t & 31, wid = t >> 5;
    s = warpReduce(s); q = warpReduce(q);
    if (lane == 0) { sh1[wid] = s; sh2[wid] = q; }
    __syncthreads();
    if (wid == 0) {
        s = (lane < 8) ? sh1[lane] : 0.f;
        q = (lane < 8) ? sh2[lane] : 0.f;
        s = warpReduce(s); q = warpReduce(q);
        if (lane == 0) {
            const float N = (float)(NB * MMs);
            float mu = s / N;
            float var = q / N - mu * mu;
            mean[ch] = mu;
            rstd[ch] = rsqrtf(var + 1e-5f);
        }
    }
}

// ---------------------------------------------------------------------------
// small kernels
// ---------------------------------------------------------------------------
__global__ void tracek0(const float* __restrict__ X, const float* __restrict__ jitter,
                        float* __restrict__ tr0, float* __restrict__ jcp)
{
    const int b = blockIdx.x;
    const int t = threadIdx.x;
    float v = X[(size_t)b * MAT + t * 257];
    float jt = 1e-10f + 1e-9f * jitter[t];
    __shared__ float sh[8], shj[8];
    const int lane = t & 31, wid = t >> 5;
    v = warpReduce(v); jt = warpReduce(jt);
    if (lane == 0) { sh[wid] = v; shj[wid] = jt; }
    __syncthreads();
    if (wid == 0) {
        v  = (lane < 8) ? sh[lane]  : 0.f;
        jt = (lane < 8) ? shj[lane] : 0.f;
        v = warpReduce(v); jt = warpReduce(jt);
        if (lane == 0) {
            tr0[b] = v;
            if (b == 0) *jcp = jt;
        }
    }
}

__global__ void scalek(float* __restrict__ C, const float* __restrict__ tr0)
{
    const int idx = blockIdx.x * 256 + threadIdx.x;
    C[idx] *= (1.0f / tr0[idx >> 16]);
}

__global__ void prep_ns(const float* __restrict__ Sm, const float* __restrict__ jitter,
                        const float* __restrict__ trp, const float* __restrict__ jcp,
                        float* __restrict__ A, float* __restrict__ ZY,
                        float* __restrict__ tr_now)
{
    const int idx = blockIdx.x * 256 + threadIdx.x;
    const int b = idx >> 16, rc = idx & 65535, r = rc >> 8, c = rc & 255;
    const float jc = *jcp;
    float t;
    if (trp != nullptr) t = trp[b*2+0] + trp[b*2+1] + jc;
    else                t = 1.0f + jc;
    float v = Sm[idx];
    if (r == c) v += 1e-10f + 1e-9f * jitter[r];
    float a = v * (1.0f / t);
    A[idx] = a;
    ZY[idx] = (r == c ? 1.5f : 0.0f) - 0.5f * a;
    if (rc == 0) tr_now[b] = t;
}

__global__ void gather_out(const float* __restrict__ L, const float* __restrict__ trp,
                           float* __restrict__ out)
{
    const int b = blockIdx.y, i = blockIdx.x, j = threadIdx.x;
    if (j < i) return;
    const float t = trp[b*2+0] + trp[b*2+1];
    const float s = rsqrtf(t);
    const int k = i * 256 - (i * (i - 1)) / 2 + (j - i);
    out[(size_t)b * 32896 + k] = L[(size_t)b * MAT + i * 256 + j] * s;
}

// ---------------------------------------------------------------------------
// Host orchestration (R12 NS structure)
// ---------------------------------------------------------------------------
static void run_inv(const float* Sm, const float* jitter, const float* trp_in,
                    float* zz, float* tr_now, const float* jcp,
                    float* A, float* Y, float* Z, float* Y2, float* Z2, float* ZYt)
{
    const dim3 g1(2, 2, NB);
    const dim3 g2(2, 2, 2 * NB);
    const float* FN = nullptr;
    float* FNm = nullptr;
    prep_ns<<<BMAT / 256, 256>>>(Sm, jitter, trp_in, jcp, A, Z, tr_now);   // Z = ZY0
    mm_gemm<<<g1, 256, MM_SMEM>>>(A, Z, Y, FN, FN, FNm, tr_now, 0, FN, 0.f, FNm);
    float *Yc = Y, *Zc = Z, *Ya = Y2, *Za = Z2;
    for (int it = 0; it < 5; it++) {
        mm_gemm<<<g1, 256, MM_SMEM>>>(Zc, Yc, ZYt, FN, FN, FNm, tr_now, 1, FN, 0.f, FNm);
        mm_gemm<<<g2, 256, MM_SMEM>>>(Yc, ZYt, Ya, ZYt, Zc, Za, tr_now, 0, FN, 0.f, FNm);
        float* t1 = Yc; Yc = Ya; Ya = t1;
        float* t2 = Zc; Zc = Za; Za = t2;
    }
    mm_gemm<<<g1, 256, MM_SMEM>>>(Zc, Yc, ZYt, FN, FN, FNm, tr_now, 1, FN, 0.f, FNm);
    mm_gemm<<<g1, 256, MM_SMEM>>>(ZYt, Zc, zz, FN, FN, FNm, tr_now, 2, FN, 0.f, FNm);
}

extern "C" void kernel_launch(void* const* d_in, const int* in_sizes, int n_in,
                              void* d_out, int out_size)
{
    (void)in_sizes; (void)n_in; (void)out_size;
    const float* x      = (const float*)d_in[0];
    const float* w      = (const float*)d_in[1];
    const float* gamma  = (const float*)d_in[2];
    const float* beta   = (const float*)d_in[3];
    const float* jitter = (const float*)d_in[4];
    float* out = (float*)d_out;

    cudaFuncSetAttribute(mm_gemm, cudaFuncAttributeMaxDynamicSharedMemorySize, MM_SMEM);
    cudaFuncSetAttribute(conv_mma, cudaFuncAttributeMaxDynamicSharedMemorySize, MM_SMEM);
    cudaFuncSetAttribute(cov_mma, cudaFuncAttributeMaxDynamicSharedMemorySize, COV_SMEM);

    float *y, *mats, *small;
    cudaGetSymbolAddress((void**)&y, g_y);
    cudaGetSymbolAddress((void**)&mats, g_mats);
    cudaGetSymbolAddress((void**)&small, g_small);

    float* Cn  = mats + 0u * BMAT;
    float* A   = mats + 1u * BMAT;
    float* Y   = mats + 2u * BMAT;
    float* Z   = mats + 3u * BMAT;
    float* Y2  = mats + 4u * BMAT;
    float* Z2  = mats + 5u * BMAT;
    float* ZYt = mats + 6u * BMAT;
    float* zz  = mats + 7u * BMAT;
    float* LLT = mats + 8u * BMAT;
    // BN partial scratch (A buffer is free until stage 3)
    float* pS  = A;
    float* pQ  = A + 256 * NPART;

    float* bn_mean = small;
    float* bn_rstd = small + 256;
    float* tr0     = small + 8704;
    float* tr_now  = small + 8736;
    float* jcp     = small + 8768;
    float* trp     = small + 8772;

    const dim3 g1(2, 2, NB);
    const float* FN = nullptr;
    float* FNm = nullptr;

    // Stage 1: conv (tensor, fused BN stat partials) + tiny BN reduce
    conv_mma<<<dim3(7, 2, NB), 256, MM_SMEM>>>(x, w, y, pS, pQ);
    bn_reduce<<<DD, 256>>>(pS, pQ, bn_mean, bn_rstd);

    // Stage 2: covariance (tensor, BN+ReLU fused in staging) + trace normalize
    cov_mma<<<dim3(3, 1, NB), 256, COV_SMEM>>>(y, bn_mean, bn_rstd, gamma, beta, Cn);
    tracek0<<<NB, 256>>>(Cn, jitter, tr0, jcp);
    scalek<<<BMAT / 256, 256>>>(Cn, tr0);

    // Stage 3: LLT = inv_sqrtm(Cn + Ij)^2 ; tr(Cn+Ij) = 1 + jc analytically
    run_inv(Cn, jitter, nullptr, zz, tr_now, jcp, A, Y, Z, Y2, Z2, ZYt);
    mm_gemm<<<g1, 256, MM_SMEM>>>(zz, zz, LLT, FN, FN, FNm, tr_now, 0, FN, 0.f, trp);

    // Stage 4: SICE loop (i=2 has dec==0 -> exact identity, skipped)
    for (int i = 0; i < 2; i++) {
        run_inv(LLT, jitter, trp, zz, tr_now, jcp, A, Y, Z, Y2, Z2, ZYt);
        const float dec = 5.0f * (1.0f - (float)i / 2.0f);
        mm_gemm<<<g1, 256, MM_SMEM>>>(zz, zz, LLT, FN, FN, FNm, tr_now, 3, Cn, dec, trp);
    }

    // Stage 5: triuvec with trace from final epi3 partials
    gather_out<<<dim3(DD, NB), 256>>>(LLT, trp, out);
}